// round 3
// baseline (speedup 1.0000x reference)
#include <cuda_runtime.h>
#include <mma.h>
#include <math.h>
#include <cstdint>

using namespace nvcuda;

#define NN    50000
#define NPAD  50048          // 391 * 128
#define EE    800000

// ---------------- scratch (device globals; no allocation) ----------------
__device__ float g_AGGX[(size_t)NPAD * 256];   // aggregated [x | perb]
__device__ float g_AGG[(size_t)NPAD * 512];    // [on_x | on_p | tg_x | tg_p]
__device__ float g_P1[(size_t)NPAD * 256];     // [h1x | h1y]
__device__ int   g_deg[NN];
__device__ int   g_off[NN + 8];
__device__ int   g_cur[NN];
__device__ int   g_scol[EE];
__device__ float g_sw[EE];
__device__ float g_bnsum[512];                 // [sum(256) | sumsq(256)]
__device__ float g_bnaff[512];                 // [scale(256) | shift(256)]
__device__ float g_c1[128];                    // b_on @ W1 + b1
__device__ float g_loss;

// ---------------- init / CSR ----------------
__global__ void k_zero() {
    int i = blockIdx.x * 256 + threadIdx.x;
    if (i < NN)  g_deg[i] = 0;
    if (i < 512) g_bnsum[i] = 0.f;
    if (i == 0)  g_loss = 0.f;
}
__global__ void k_hist(const int* __restrict__ row) {
    int e = blockIdx.x * 256 + threadIdx.x;
    if (e < EE) atomicAdd(&g_deg[row[e]], 1);
}
__global__ void k_scan() {
    __shared__ int swarp[32];
    int t = threadIdx.x, lane = t & 31, wid = t >> 5;
    int running = 0;
    for (int base = 0; base < NN; base += 1024) {
        int idx = base + t;
        int v = (idx < NN) ? g_deg[idx] : 0;
        int incl = v;
        #pragma unroll
        for (int s = 1; s < 32; s <<= 1) {
            int a = __shfl_up_sync(0xFFFFFFFFu, incl, s);
            if (lane >= s) incl += a;
        }
        if (lane == 31) swarp[wid] = incl;
        __syncthreads();
        if (wid == 0) {
            int wv = swarp[lane];
            #pragma unroll
            for (int s = 1; s < 32; s <<= 1) {
                int a = __shfl_up_sync(0xFFFFFFFFu, wv, s);
                if (lane >= s) wv += a;
            }
            swarp[lane] = wv;
        }
        __syncthreads();
        int pre = (wid > 0) ? swarp[wid - 1] : 0;
        int excl = running + pre + incl - v;
        if (idx < NN) { g_off[idx] = excl; g_cur[idx] = excl; }
        running += swarp[31];
        __syncthreads();
    }
    if (t == 0) g_off[NN] = running;
}
__global__ void k_scatter(const int* __restrict__ row, const int* __restrict__ col,
                          const float* __restrict__ w) {
    int e = blockIdx.x * 256 + threadIdx.x;
    if (e < EE) {
        int r = row[e];
        int p = atomicAdd(&g_cur[r], 1);
        g_scol[p] = col[e];
        g_sw[p]   = w[e];
    }
}

// ---------------- sparse aggregation of raw [x | perb] ----------------
__global__ __launch_bounds__(128) void k_aggregate(const float* __restrict__ x,
                                                   const float* __restrict__ perb) {
    int t = threadIdx.x, lane = t & 31, wid = t >> 5;
    int r = blockIdx.x * 2 + (wid >> 1);
    int part = wid & 1;
    const float4* src = part ? (const float4*)perb : (const float4*)x;
    int s = g_off[r], e = g_off[r + 1];
    float ax = 0.f, ay = 0.f, az = 0.f, aw = 0.f;
    int i = s;
    for (; i + 4 <= e; i += 4) {
        int c0 = g_scol[i], c1 = g_scol[i + 1], c2 = g_scol[i + 2], c3 = g_scol[i + 3];
        float w0 = g_sw[i], w1 = g_sw[i + 1], w2 = g_sw[i + 2], w3 = g_sw[i + 3];
        float4 h0 = src[(size_t)c0 * 32 + lane];
        float4 h1 = src[(size_t)c1 * 32 + lane];
        float4 h2 = src[(size_t)c2 * 32 + lane];
        float4 h3 = src[(size_t)c3 * 32 + lane];
        ax += w0 * h0.x + w1 * h1.x + w2 * h2.x + w3 * h3.x;
        ay += w0 * h0.y + w1 * h1.y + w2 * h2.y + w3 * h3.y;
        az += w0 * h0.z + w1 * h1.z + w2 * h2.z + w3 * h3.z;
        aw += w0 * h0.w + w1 * h1.w + w2 * h2.w + w3 * h3.w;
    }
    for (; i < e; i++) {
        int c = g_scol[i]; float w = g_sw[i];
        float4 h = src[(size_t)c * 32 + lane];
        ax += w * h.x; ay += w * h.y; az += w * h.z; aw += w * h.w;
    }
    ((float4*)g_AGGX)[(size_t)r * 64 + part * 32 + lane] = make_float4(ax, ay, az, aw);
}

// ---------------- wmma tf32 split-GEMM helpers ----------------
typedef wmma::fragment<wmma::matrix_a, 16, 16, 8, wmma::precision::tf32, wmma::row_major> FragA;
typedef wmma::fragment<wmma::matrix_b, 16, 16, 8, wmma::precision::tf32, wmma::row_major> FragB;
typedef wmma::fragment<wmma::accumulator, 16, 16, 8, float> FragC;

__device__ __forceinline__ void split_a_vals(FragA& a, FragA& ah, FragA& al) {
    #pragma unroll
    for (int i = 0; i < a.num_elements; i++) {
        float v = a.x[i];
        float h = wmma::__float_to_tf32(v);
        ah.x[i] = h;
        al.x[i] = wmma::__float_to_tf32(v - h);
    }
}
__device__ __forceinline__ void split_b(const float* p, int ld, FragB& bh, FragB& bl) {
    FragB b;
    wmma::load_matrix_sync(b, p, ld);
    #pragma unroll
    for (int i = 0; i < b.num_elements; i++) {
        float v = b.x[i];
        float h = wmma::__float_to_tf32(v);
        bh.x[i] = h;
        bl.x[i] = wmma::__float_to_tf32(v - h);
    }
}
// acc[8] += A_strip(16x128) @ B(128x128);  A from (ap, lda), B from (bp, 128)
__device__ __forceinline__ void mm_strip(FragC acc[8], const float* ap, int lda,
                                         const float* ap2, const float* bp) {
    #pragma unroll 1
    for (int ks = 0; ks < 16; ks++) {
        FragA a, ah, al;
        wmma::load_matrix_sync(a, ap + ks * 8, lda);
        if (ap2) {
            FragA a2;
            wmma::load_matrix_sync(a2, ap2 + ks * 8, lda);
            #pragma unroll
            for (int i = 0; i < a.num_elements; i++) a.x[i] += a2.x[i];
        }
        split_a_vals(a, ah, al);
        #pragma unroll
        for (int ct = 0; ct < 8; ct++) {
            FragB bh, bl;
            split_b(bp + ks * 8 * 128 + ct * 16, 128, bh, bl);
            wmma::mma_sync(acc[ct], ah, bh, acc[ct]);
            wmma::mma_sync(acc[ct], ah, bl, acc[ct]);
            wmma::mma_sync(acc[ct], al, bh, acc[ct]);
        }
    }
}

// ---------------- c1 = b_on @ W1 + b1 ----------------
__global__ void k_c1(const float* __restrict__ b_on, const float* __restrict__ W1,
                     const float* __restrict__ b1) {
    int n = threadIdx.x;
    float s = b1[n];
    for (int k = 0; k < 128; k++) s += b_on[k] * W1[k * 128 + n];
    g_c1[n] = s;
}

// ---------------- feature GEMMs: AGG[:,sec*128:+128] = AGGX_part @ W ----------------
__global__ __launch_bounds__(256) void k_mm_feat(const float* __restrict__ W_on,
                                                 const float* __restrict__ W_tg) {
    int sec = blockIdx.y, row0 = blockIdx.x * 128;
    int wid = threadIdx.x >> 5;
    const float* A = g_AGGX + ((size_t)row0 + wid * 16) * 256 + (sec & 1) * 128;
    const float* W = (sec < 2) ? W_on : W_tg;
    FragC acc[8];
    #pragma unroll
    for (int i = 0; i < 8; i++) wmma::fill_fragment(acc[i], 0.f);
    mm_strip(acc, A, 256, nullptr, W);
    float* Out = g_AGG + ((size_t)row0 + wid * 16) * 512 + sec * 128;
    #pragma unroll
    for (int ct = 0; ct < 8; ct++)
        wmma::store_matrix_sync(Out + ct * 16, acc[ct], 512, wmma::mem_row_major);
}

// ---------------- embed = x + perb + agg_on_x + agg_on_p + b_on ----------------
__global__ void k_embed(const float* __restrict__ x, const float* __restrict__ perb,
                        const float* __restrict__ b_on, float* __restrict__ out) {
    int id = blockIdx.x * 256 + threadIdx.x;  // float4 index
    if (id < NN * 32) {
        int r = id >> 5, c = id & 31;
        float4 xv = ((const float4*)x)[id];
        float4 pv = ((const float4*)perb)[id];
        float4 a0 = ((const float4*)g_AGG)[(size_t)r * 128 + c];
        float4 a1 = ((const float4*)g_AGG)[(size_t)r * 128 + 32 + c];
        float4 bv = ((const float4*)b_on)[c];
        ((float4*)out)[id] = make_float4(xv.x + pv.x + a0.x + a1.x + bv.x,
                                         xv.y + pv.y + a0.y + a1.y + bv.y,
                                         xv.z + pv.z + a0.z + a1.z + bv.z,
                                         xv.w + pv.w + a0.w + a1.w + bv.w);
    }
}

#define STG_LD 136
#define DYN_SMEM (128 * STG_LD * 4)

// ---------------- pred stage 1: P1 = online @ W1 + c1 ; fused BN stats ----------------
__global__ __launch_bounds__(256) void k_mm_p1(const float* __restrict__ W1) {
    extern __shared__ float stg[];   // 128 x 136
    int sec = blockIdx.y, row0 = blockIdx.x * 128;
    int t = threadIdx.x, wid = t >> 5;
    const float* A = g_AGG + ((size_t)row0 + wid * 16) * 512;
    const float* A2 = sec ? (A + 128) : nullptr;
    FragC acc[8];
    #pragma unroll
    for (int i = 0; i < 8; i++) wmma::fill_fragment(acc[i], 0.f);
    mm_strip(acc, A, 512, A2, W1);
    #pragma unroll
    for (int ct = 0; ct < 8; ct++)
        wmma::store_matrix_sync(stg + wid * 16 * STG_LD + ct * 16, acc[ct], STG_LD,
                                wmma::mem_row_major);
    __syncthreads();
    float* Out = g_P1 + (size_t)row0 * 256 + sec * 128;
    #pragma unroll
    for (int i = 0; i < 64; i++) {
        int idx = t + i * 256;
        int r = idx >> 7, c = idx & 127;
        float v = stg[r * STG_LD + c] + g_c1[c];
        Out[(size_t)r * 256 + c] = v;
        stg[r * STG_LD + c] = v;
    }
    __syncthreads();
    if (t < 128) {
        float s = 0.f, q = 0.f;
        int rmax = NN - row0; if (rmax > 128) rmax = 128;
        for (int r = 0; r < rmax; r++) {
            float v = stg[r * STG_LD + t];
            s += v; q += v * v;
        }
        atomicAdd(&g_bnsum[sec * 128 + t], s);
        atomicAdd(&g_bnsum[256 + sec * 128 + t], q);
    }
}

__global__ void k_bn_final(const float* __restrict__ bn_g, const float* __restrict__ bn_b) {
    int t = threadIdx.x;  // 0..255
    float inv_n = 1.f / (float)NN;
    float mean = g_bnsum[t] * inv_n;
    float var = g_bnsum[256 + t] * inv_n - mean * mean;
    int f = t & 127;
    float sc = bn_g[f] * rsqrtf(var + 1e-5f);
    g_bnaff[t] = sc;
    g_bnaff[256 + t] = bn_b[f] - mean * sc;
}

// ---------------- pred stage 2 + cosine loss (P2 never leaves the block) ----------------
__global__ __launch_bounds__(256) void k_mm_p2(const float* __restrict__ b_tg,
                                               const float* __restrict__ prelu_a,
                                               const float* __restrict__ W2,
                                               const float* __restrict__ b2) {
    extern __shared__ float stg[];   // 128 x 136
    __shared__ float warp_l[8];
    int sec = blockIdx.y, row0 = blockIdx.x * 128;
    int t = threadIdx.x, wid = t >> 5, lane = t & 31;
    float alpha = prelu_a[0];

    // stage A = PReLU(BN(P1)) into smem
    #pragma unroll
    for (int i = 0; i < 64; i++) {
        int idx = t + i * 256;
        int r = idx >> 7, c = idx & 127;
        float v = g_P1[((size_t)row0 + r) * 256 + sec * 128 + c] * g_bnaff[sec * 128 + c]
                  + g_bnaff[256 + sec * 128 + c];
        stg[r * STG_LD + c] = v > 0.f ? v : alpha * v;
    }
    __syncthreads();

    FragC acc[8];
    #pragma unroll
    for (int i = 0; i < 8; i++) wmma::fill_fragment(acc[i], 0.f);
    mm_strip(acc, stg + wid * 16 * STG_LD, STG_LD, nullptr, W2);

    // each warp's A strip is private: safe to overwrite own strip with results
    #pragma unroll
    for (int ct = 0; ct < 8; ct++)
        wmma::store_matrix_sync(stg + wid * 16 * STG_LD + ct * 16, acc[ct], STG_LD,
                                wmma::mem_row_major);
    __syncwarp();

    float4 bb = *(const float4*)(b2 + lane * 4);
    float4 bt = *(const float4*)(b_tg + lane * 4);
    float lsum = 0.f;
    for (int rr = 0; rr < 16; rr++) {
        int r = wid * 16 + rr;
        int gr = row0 + r;
        if (gr < NN) {
            float p0 = stg[r * STG_LD + lane * 4]     + bb.x;
            float p1 = stg[r * STG_LD + lane * 4 + 1] + bb.y;
            float p2 = stg[r * STG_LD + lane * 4 + 2] + bb.z;
            float p3 = stg[r * STG_LD + lane * 4 + 3] + bb.w;
            float4 tg = *(const float4*)(g_AGG + (size_t)gr * 512 + 256 + lane * 4);
            if (sec == 0) {  // target_x = agg_tg_x + agg_tg_p + b_tg
                float4 u = *(const float4*)(g_AGG + (size_t)gr * 512 + 384 + lane * 4);
                tg.x += u.x; tg.y += u.y; tg.z += u.z; tg.w += u.w;
            }
            tg.x += bt.x; tg.y += bt.y; tg.z += bt.z; tg.w += bt.w;
            float dot = p0 * tg.x + p1 * tg.y + p2 * tg.z + p3 * tg.w;
            float np  = p0 * p0 + p1 * p1 + p2 * p2 + p3 * p3;
            float nt  = tg.x * tg.x + tg.y * tg.y + tg.z * tg.z + tg.w * tg.w;
            #pragma unroll
            for (int s = 16; s; s >>= 1) {
                dot += __shfl_xor_sync(0xFFFFFFFFu, dot, s);
                np  += __shfl_xor_sync(0xFFFFFFFFu, np, s);
                nt  += __shfl_xor_sync(0xFFFFFFFFu, nt, s);
            }
            if (lane == 0) {
                float d1 = fmaxf(sqrtf(np), 1e-12f);
                float d2 = fmaxf(sqrtf(nt), 1e-12f);
                lsum += 2.f - 2.f * dot / (d1 * d2);
            }
        }
    }
    if (lane == 0) warp_l[wid] = lsum;
    __syncthreads();
    if (t == 0) {
        float s = 0.f;
        #pragma unroll
        for (int w = 0; w < 8; w++) s += warp_l[w];
        atomicAdd(&g_loss, s);
    }
}

__global__ void k_final(float* out, int out_size) {
    out[out_size - 1] = g_loss * (1.f / (float)NN);
}

// ---------------- host ----------------
extern "C" void kernel_launch(void* const* d_in, const int* in_sizes, int n_in,
                              void* d_out, int out_size) {
    const float* x       = (const float*)d_in[0];
    const float* perb    = (const float*)d_in[1];
    const int*   erow    = (const int*)d_in[2];
    const int*   ecol    = (const int*)d_in[3];
    const float* ew      = (const float*)d_in[4];
    const float* W_on    = (const float*)d_in[5];
    const float* b_on    = (const float*)d_in[6];
    const float* W_tg    = (const float*)d_in[7];
    const float* b_tg    = (const float*)d_in[8];
    const float* W1      = (const float*)d_in[9];
    const float* b1      = (const float*)d_in[10];
    const float* bn_g    = (const float*)d_in[11];
    const float* bn_b    = (const float*)d_in[12];
    const float* prelu_a = (const float*)d_in[13];
    const float* W2      = (const float*)d_in[14];
    const float* b2      = (const float*)d_in[15];
    float* out = (float*)d_out;

    cudaFuncSetAttribute(k_mm_p1, cudaFuncAttributeMaxDynamicSharedMemorySize, DYN_SMEM);
    cudaFuncSetAttribute(k_mm_p2, cudaFuncAttributeMaxDynamicSharedMemorySize, DYN_SMEM);

    k_zero<<<196, 256>>>();
    k_hist<<<3125, 256>>>(erow);
    k_c1<<<1, 128>>>(b_on, W1, b1);
    k_scan<<<1, 1024>>>();
    k_scatter<<<3125, 256>>>(erow, ecol, ew);
    k_aggregate<<<25000, 128>>>(x, perb);
    k_mm_feat<<<dim3(391, 4), 256>>>(W_on, W_tg);
    k_embed<<<6250, 256>>>(x, perb, b_on, out);
    k_mm_p1<<<dim3(391, 2), 256, DYN_SMEM>>>(W1);
    k_bn_final<<<1, 256>>>(bn_g, bn_b);
    k_mm_p2<<<dim3(391, 2), 256, DYN_SMEM>>>(b_tg, prelu_a, W2, b2);
    k_final<<<1, 1>>>(out, out_size);
}

// round 4
// speedup vs baseline: 1.5289x; 1.5289x over previous
#include <cuda_runtime.h>
#include <mma.h>
#include <math.h>
#include <cstdint>

using namespace nvcuda;

#define NN    50000
#define NPAD  50048          // 391 * 128
#define EE    800000

// ---------------- scratch (device globals; no allocation) ----------------
__device__ float g_AGGX[(size_t)NPAD * 256];   // aggregated [x | perb]
__device__ float g_AGG[(size_t)NPAD * 512];    // [on_x | on_p | tg_x | tg_p]
__device__ float g_P1[(size_t)NPAD * 256];     // [h1x | h1y]
__device__ int   g_deg[NN];
__device__ int   g_off[NN + 8];
__device__ int   g_cur[NN];
__device__ int   g_btot[64];
__device__ int   g_scol[EE];
__device__ float g_sw[EE];
__device__ float g_bnsum[512];                 // [sum(256) | sumsq(256)]
__device__ float g_bnaff[512];                 // [scale(256) | shift(256)]
__device__ float g_c1[128];                    // b_on @ W1 + b1
__device__ float g_loss;

// ---------------- init ----------------
__global__ void k_zero() {
    int i = blockIdx.x * 256 + threadIdx.x;
    if (i < NN)  g_deg[i] = 0;
    if (i < 512) g_bnsum[i] = 0.f;
    if (i == 0)  g_loss = 0.f;
}
__global__ void k_hist(const int* __restrict__ row) {
    int e = blockIdx.x * 256 + threadIdx.x;
    if (e < EE) atomicAdd(&g_deg[row[e]], 1);
}

// ---------------- 3-pass scan ----------------
__global__ __launch_bounds__(1024) void k_scan1() {
    __shared__ int wsum[32];
    int t = threadIdx.x, lane = t & 31, wid = t >> 5;
    int idx = blockIdx.x * 1024 + t;
    int v = (idx < NN) ? g_deg[idx] : 0;
    int incl = v;
    #pragma unroll
    for (int s = 1; s < 32; s <<= 1) {
        int a = __shfl_up_sync(0xFFFFFFFFu, incl, s);
        if (lane >= s) incl += a;
    }
    if (lane == 31) wsum[wid] = incl;
    __syncthreads();
    if (wid == 0) {
        int wv = wsum[lane];
        #pragma unroll
        for (int s = 1; s < 32; s <<= 1) {
            int a = __shfl_up_sync(0xFFFFFFFFu, wv, s);
            if (lane >= s) wv += a;
        }
        wsum[lane] = wv;
    }
    __syncthreads();
    int excl = (wid > 0 ? wsum[wid - 1] : 0) + incl - v;
    if (idx < NN) g_off[idx] = excl;
    if (t == 0) g_btot[blockIdx.x] = wsum[31];
}
__global__ void k_scan2() {
    if (threadIdx.x == 0) {
        int run = 0;
        for (int i = 0; i < 49; i++) { int v = g_btot[i]; g_btot[i] = run; run += v; }
        g_off[NN] = run;
    }
}
__global__ __launch_bounds__(1024) void k_scan3() {
    int idx = blockIdx.x * 1024 + threadIdx.x;
    if (idx < NN) {
        int o = g_off[idx] + g_btot[blockIdx.x];
        g_off[idx] = o;
        g_cur[idx] = o;
    }
}
__global__ void k_scatter(const int* __restrict__ row, const int* __restrict__ col,
                          const float* __restrict__ w) {
    int e = blockIdx.x * 256 + threadIdx.x;
    if (e < EE) {
        int r = row[e];
        int p = atomicAdd(&g_cur[r], 1);
        g_scol[p] = col[e];
        g_sw[p]   = w[e];
    }
}

// ---------------- sparse aggregation of raw [x | perb] ----------------
__global__ __launch_bounds__(128) void k_aggregate(const float* __restrict__ x,
                                                   const float* __restrict__ perb) {
    int t = threadIdx.x, lane = t & 31, wid = t >> 5;
    int r = blockIdx.x * 2 + (wid >> 1);
    int part = wid & 1;
    const float4* src = part ? (const float4*)perb : (const float4*)x;
    int s = g_off[r], e = g_off[r + 1];
    float ax = 0.f, ay = 0.f, az = 0.f, aw = 0.f;
    int i = s;
    for (; i + 4 <= e; i += 4) {
        int c0 = g_scol[i], c1 = g_scol[i + 1], c2 = g_scol[i + 2], c3 = g_scol[i + 3];
        float w0 = g_sw[i], w1 = g_sw[i + 1], w2 = g_sw[i + 2], w3 = g_sw[i + 3];
        float4 h0 = src[(size_t)c0 * 32 + lane];
        float4 h1 = src[(size_t)c1 * 32 + lane];
        float4 h2 = src[(size_t)c2 * 32 + lane];
        float4 h3 = src[(size_t)c3 * 32 + lane];
        ax += w0 * h0.x + w1 * h1.x + w2 * h2.x + w3 * h3.x;
        ay += w0 * h0.y + w1 * h1.y + w2 * h2.y + w3 * h3.y;
        az += w0 * h0.z + w1 * h1.z + w2 * h2.z + w3 * h3.z;
        aw += w0 * h0.w + w1 * h1.w + w2 * h2.w + w3 * h3.w;
    }
    for (; i < e; i++) {
        int c = g_scol[i]; float w = g_sw[i];
        float4 h = src[(size_t)c * 32 + lane];
        ax += w * h.x; ay += w * h.y; az += w * h.z; aw += w * h.w;
    }
    ((float4*)g_AGGX)[(size_t)r * 64 + part * 32 + lane] = make_float4(ax, ay, az, aw);
}

// ---------------- wmma tf32 split-GEMM, smem-staged ----------------
typedef wmma::fragment<wmma::matrix_a, 16, 16, 8, wmma::precision::tf32, wmma::row_major> FragA;
typedef wmma::fragment<wmma::matrix_b, 16, 16, 8, wmma::precision::tf32, wmma::row_major> FragB;
typedef wmma::fragment<wmma::accumulator, 16, 16, 8, float> FragC;

#define SLD   132
#define SM_A  0
#define SM_BH (128 * SLD)
#define SM_BL (2 * 128 * SLD)
#define DYN_SMEM (3 * 128 * SLD * 4)   // 202752 bytes

// stage W (128x128 row-major) split into tf32 hi/lo smem images; coalesced
__device__ __forceinline__ void stage_B(float* sm, const float* __restrict__ W, int t) {
    float* bh = sm + SM_BH;
    float* bl = sm + SM_BL;
    #pragma unroll
    for (int i = 0; i < 64; i++) {
        int idx = t + i * 256;
        int r = idx >> 7, c = idx & 127;
        float v = W[idx];
        float h = wmma::__float_to_tf32(v);
        bh[r * SLD + c] = h;
        bl[r * SLD + c] = wmma::__float_to_tf32(v - h);
    }
}

// block GEMM: sA(128x128 fp32, ld SLD) @ sB(128x128 hi/lo) -> acc[4][2]
// warp (wm = wid>>2 in 0..1, wn = wid&3 in 0..3) owns rows wm*64..+63, cols wn*32..+31
__device__ __forceinline__ void mm_block(const float* sm, FragC acc[4][2], int wid) {
    int wm = wid >> 2, wn = wid & 3;
    const float* A  = sm + SM_A + wm * 64 * SLD;
    const float* BH = sm + SM_BH + wn * 32;
    const float* BL = sm + SM_BL + wn * 32;
    #pragma unroll
    for (int m = 0; m < 4; m++)
        #pragma unroll
        for (int ct = 0; ct < 2; ct++) wmma::fill_fragment(acc[m][ct], 0.f);
    #pragma unroll 1
    for (int ks = 0; ks < 16; ks++) {
        FragA ah[4], al[4];
        #pragma unroll
        for (int m = 0; m < 4; m++) {
            FragA a;
            wmma::load_matrix_sync(a, A + m * 16 * SLD + ks * 8, SLD);
            #pragma unroll
            for (int i = 0; i < 4; i++) {
                float v = a.x[i];
                float h = wmma::__float_to_tf32(v);
                ah[m].x[i] = h;
                al[m].x[i] = wmma::__float_to_tf32(v - h);
            }
        }
        #pragma unroll
        for (int ct = 0; ct < 2; ct++) {
            FragB bh, bl;
            wmma::load_matrix_sync(bh, BH + ks * 8 * SLD + ct * 16, SLD);
            wmma::load_matrix_sync(bl, BL + ks * 8 * SLD + ct * 16, SLD);
            #pragma unroll
            for (int m = 0; m < 4; m++) {
                wmma::mma_sync(acc[m][ct], ah[m], bh, acc[m][ct]);
                wmma::mma_sync(acc[m][ct], ah[m], bl, acc[m][ct]);
                wmma::mma_sync(acc[m][ct], al[m], bh, acc[m][ct]);
            }
        }
    }
}

// ---------------- c1 = b_on @ W1 + b1 ----------------
__global__ void k_c1(const float* __restrict__ b_on, const float* __restrict__ W1,
                     const float* __restrict__ b1) {
    int n = threadIdx.x;
    float s = b1[n];
    for (int k = 0; k < 128; k++) s += b_on[k] * W1[k * 128 + n];
    g_c1[n] = s;
}

// ---------------- feature GEMMs: AGG[:,sec*128:+128] = AGGX_part @ W ----------------
__global__ __launch_bounds__(256) void k_mm_feat(const float* __restrict__ W_on,
                                                 const float* __restrict__ W_tg) {
    extern __shared__ float sm[];
    int t = threadIdx.x, wid = t >> 5;
    int sec = blockIdx.y, row0 = blockIdx.x * 128;
    stage_B(sm, (sec < 2) ? W_on : W_tg, t);
    const float* A = g_AGGX + (size_t)row0 * 256 + (sec & 1) * 128;
    #pragma unroll
    for (int i = 0; i < 64; i++) {
        int idx = t + i * 256;
        int r = idx >> 7, c = idx & 127;
        sm[r * SLD + c] = A[(size_t)r * 256 + c];
    }
    __syncthreads();
    FragC acc[4][2];
    mm_block(sm, acc, wid);
    int wm = wid >> 2, wn = wid & 3;
    float* Out = g_AGG + ((size_t)row0 + wm * 64) * 512 + sec * 128 + wn * 32;
    #pragma unroll
    for (int m = 0; m < 4; m++)
        #pragma unroll
        for (int ct = 0; ct < 2; ct++)
            wmma::store_matrix_sync(Out + (size_t)m * 16 * 512 + ct * 16, acc[m][ct], 512,
                                    wmma::mem_row_major);
}

// ---------------- embed = x + perb + agg_on_x + agg_on_p + b_on ----------------
__global__ void k_embed(const float* __restrict__ x, const float* __restrict__ perb,
                        const float* __restrict__ b_on, float* __restrict__ out) {
    int id = blockIdx.x * 256 + threadIdx.x;  // float4 index
    if (id < NN * 32) {
        int r = id >> 5, c = id & 31;
        float4 xv = ((const float4*)x)[id];
        float4 pv = ((const float4*)perb)[id];
        float4 a0 = ((const float4*)g_AGG)[(size_t)r * 128 + c];
        float4 a1 = ((const float4*)g_AGG)[(size_t)r * 128 + 32 + c];
        float4 bv = ((const float4*)b_on)[c];
        ((float4*)out)[id] = make_float4(xv.x + pv.x + a0.x + a1.x + bv.x,
                                         xv.y + pv.y + a0.y + a1.y + bv.y,
                                         xv.z + pv.z + a0.z + a1.z + bv.z,
                                         xv.w + pv.w + a0.w + a1.w + bv.w);
    }
}

// ---------------- pred stage 1: P1 = online @ W1 + c1 ; fused BN stats ----------------
__global__ __launch_bounds__(256) void k_mm_p1(const float* __restrict__ W1) {
    extern __shared__ float sm[];
    int t = threadIdx.x, wid = t >> 5;
    int sec = blockIdx.y, row0 = blockIdx.x * 128;
    stage_B(sm, W1, t);
    #pragma unroll
    for (int i = 0; i < 64; i++) {
        int idx = t + i * 256;
        int r = idx >> 7, c = idx & 127;
        float v = g_AGG[((size_t)row0 + r) * 512 + c];
        if (sec) v += g_AGG[((size_t)row0 + r) * 512 + 128 + c];
        sm[r * SLD + c] = v;
    }
    __syncthreads();
    FragC acc[4][2];
    mm_block(sm, acc, wid);
    __syncthreads();   // everyone done reading sA
    int wm = wid >> 2, wn = wid & 3;
    #pragma unroll
    for (int m = 0; m < 4; m++)
        #pragma unroll
        for (int ct = 0; ct < 2; ct++)
            wmma::store_matrix_sync(sm + (wm * 64 + m * 16) * SLD + wn * 32 + ct * 16,
                                    acc[m][ct], SLD, wmma::mem_row_major);
    __syncthreads();
    float* Out = g_P1 + (size_t)row0 * 256 + sec * 128;
    #pragma unroll
    for (int i = 0; i < 64; i++) {
        int idx = t + i * 256;
        int r = idx >> 7, c = idx & 127;
        float v = sm[r * SLD + c] + g_c1[c];
        Out[(size_t)r * 256 + c] = v;
        sm[r * SLD + c] = v;
    }
    __syncthreads();
    if (t < 128) {
        float s = 0.f, q = 0.f;
        int rmax = NN - row0; if (rmax > 128) rmax = 128;
        for (int r = 0; r < rmax; r++) {
            float v = sm[r * SLD + t];
            s += v; q += v * v;
        }
        atomicAdd(&g_bnsum[sec * 128 + t], s);
        atomicAdd(&g_bnsum[256 + sec * 128 + t], q);
    }
}

__global__ void k_bn_final(const float* __restrict__ bn_g, const float* __restrict__ bn_b) {
    int t = threadIdx.x;  // 0..255
    float inv_n = 1.f / (float)NN;
    float mean = g_bnsum[t] * inv_n;
    float var = g_bnsum[256 + t] * inv_n - mean * mean;
    int f = t & 127;
    float sc = bn_g[f] * rsqrtf(var + 1e-5f);
    g_bnaff[t] = sc;
    g_bnaff[256 + t] = bn_b[f] - mean * sc;
}

// ---------------- pred stage 2 + cosine loss (P2 never leaves the block) ----------------
__global__ __launch_bounds__(256) void k_mm_p2(const float* __restrict__ b_tg,
                                               const float* __restrict__ prelu_a,
                                               const float* __restrict__ W2,
                                               const float* __restrict__ b2) {
    extern __shared__ float sm[];
    __shared__ float warp_l[8];
    int t = threadIdx.x, wid = t >> 5, lane = t & 31;
    int sec = blockIdx.y, row0 = blockIdx.x * 128;
    float alpha = prelu_a[0];
    stage_B(sm, W2, t);
    #pragma unroll
    for (int i = 0; i < 64; i++) {
        int idx = t + i * 256;
        int r = idx >> 7, c = idx & 127;
        float v = g_P1[((size_t)row0 + r) * 256 + sec * 128 + c] * g_bnaff[sec * 128 + c]
                  + g_bnaff[256 + sec * 128 + c];
        sm[r * SLD + c] = v > 0.f ? v : alpha * v;
    }
    __syncthreads();
    FragC acc[4][2];
    mm_block(sm, acc, wid);
    __syncthreads();
    int wm = wid >> 2, wn = wid & 3;
    #pragma unroll
    for (int m = 0; m < 4; m++)
        #pragma unroll
        for (int ct = 0; ct < 2; ct++)
            wmma::store_matrix_sync(sm + (wm * 64 + m * 16) * SLD + wn * 32 + ct * 16,
                                    acc[m][ct], SLD, wmma::mem_row_major);
    __syncthreads();

    float4 bb = *(const float4*)(b2 + lane * 4);
    float4 bt = *(const float4*)(b_tg + lane * 4);
    float lsum = 0.f;
    for (int rr = 0; rr < 16; rr++) {
        int r = wid * 16 + rr;
        int gr = row0 + r;
        if (gr < NN) {
            float p0 = sm[r * SLD + lane * 4]     + bb.x;
            float p1 = sm[r * SLD + lane * 4 + 1] + bb.y;
            float p2 = sm[r * SLD + lane * 4 + 2] + bb.z;
            float p3 = sm[r * SLD + lane * 4 + 3] + bb.w;
            float4 tg = *(const float4*)(g_AGG + (size_t)gr * 512 + 256 + lane * 4);
            if (sec == 0) {  // target_x = agg_tg_x + agg_tg_p + b_tg
                float4 u = *(const float4*)(g_AGG + (size_t)gr * 512 + 384 + lane * 4);
                tg.x += u.x; tg.y += u.y; tg.z += u.z; tg.w += u.w;
            }
            tg.x += bt.x; tg.y += bt.y; tg.z += bt.z; tg.w += bt.w;
            float dot = p0 * tg.x + p1 * tg.y + p2 * tg.z + p3 * tg.w;
            float np  = p0 * p0 + p1 * p1 + p2 * p2 + p3 * p3;
            float nt  = tg.x * tg.x + tg.y * tg.y + tg.z * tg.z + tg.w * tg.w;
            #pragma unroll
            for (int s = 16; s; s >>= 1) {
                dot += __shfl_xor_sync(0xFFFFFFFFu, dot, s);
                np  += __shfl_xor_sync(0xFFFFFFFFu, np, s);
                nt  += __shfl_xor_sync(0xFFFFFFFFu, nt, s);
            }
            if (lane == 0) {
                float d1 = fmaxf(sqrtf(np), 1e-12f);
                float d2 = fmaxf(sqrtf(nt), 1e-12f);
                lsum += 2.f - 2.f * dot / (d1 * d2);
            }
        }
    }
    if (lane == 0) warp_l[wid] = lsum;
    __syncthreads();
    if (t == 0) {
        float s = 0.f;
        #pragma unroll
        for (int w = 0; w < 8; w++) s += warp_l[w];
        atomicAdd(&g_loss, s);
    }
}

__global__ void k_final(float* out, int out_size) {
    out[out_size - 1] = g_loss * (1.f / (float)NN);
}

// ---------------- host ----------------
extern "C" void kernel_launch(void* const* d_in, const int* in_sizes, int n_in,
                              void* d_out, int out_size) {
    const float* x       = (const float*)d_in[0];
    const float* perb    = (const float*)d_in[1];
    const int*   erow    = (const int*)d_in[2];
    const int*   ecol    = (const int*)d_in[3];
    const float* ew      = (const float*)d_in[4];
    const float* W_on    = (const float*)d_in[5];
    const float* b_on    = (const float*)d_in[6];
    const float* W_tg    = (const float*)d_in[7];
    const float* b_tg    = (const float*)d_in[8];
    const float* W1      = (const float*)d_in[9];
    const float* b1      = (const float*)d_in[10];
    const float* bn_g    = (const float*)d_in[11];
    const float* bn_b    = (const float*)d_in[12];
    const float* prelu_a = (const float*)d_in[13];
    const float* W2      = (const float*)d_in[14];
    const float* b2      = (const float*)d_in[15];
    float* out = (float*)d_out;

    cudaFuncSetAttribute(k_mm_feat, cudaFuncAttributeMaxDynamicSharedMemorySize, DYN_SMEM);
    cudaFuncSetAttribute(k_mm_p1,   cudaFuncAttributeMaxDynamicSharedMemorySize, DYN_SMEM);
    cudaFuncSetAttribute(k_mm_p2,   cudaFuncAttributeMaxDynamicSharedMemorySize, DYN_SMEM);

    k_zero<<<196, 256>>>();
    k_hist<<<3125, 256>>>(erow);
    k_c1<<<1, 128>>>(b_on, W1, b1);
    k_scan1<<<49, 1024>>>();
    k_scan2<<<1, 32>>>();
    k_scan3<<<49, 1024>>>();
    k_scatter<<<3125, 256>>>(erow, ecol, ew);
    k_aggregate<<<25000, 128>>>(x, perb);
    k_mm_feat<<<dim3(391, 4), 256, DYN_SMEM>>>(W_on, W_tg);
    k_embed<<<6250, 256>>>(x, perb, b_on, out);
    k_mm_p1<<<dim3(391, 2), 256, DYN_SMEM>>>(W1);
    k_bn_final<<<1, 256>>>(bn_g, bn_b);
    k_mm_p2<<<dim3(391, 2), 256, DYN_SMEM>>>(b_tg, prelu_a, W2, b2);
    k_final<<<1, 1>>>(out, out_size);
}